// round 4
// baseline (speedup 1.0000x reference)
#include <cuda_runtime.h>
#include <math.h>

#define NN 50000
#define EE 625000
#define DD 128
#define ROWS_PER_BLOCK 64
#define GEMM_THREADS 256
#define SCAN_T 1024

// Scratch (device globals — no allocation allowed in kernel_launch)
__device__ int   g_deg[2 * NN];                 // [0:NN) fwd in-deg by dst, [NN:2NN) bwd by src
__device__ int   g_off[2 * NN];                 // CSR row starts
__device__ int   g_cur[2 * NN];                 // fill cursors
__device__ int   g_csr[2 * EE];                 // neighbor lists (both convs concatenated)
__device__ float g_hs_f[(size_t)NN * DD];       // (x@W_fwd) * dinv_f  (row-scaled)
__device__ float g_hs_b[(size_t)NN * DD];

__global__ void k_init_deg() {
    int i = blockIdx.x * blockDim.x + threadIdx.x;
    if (i < 2 * NN) g_deg[i] = 0;
}

// 2 edges per thread for atomic MLP
__global__ void k_count(const int* __restrict__ ei) {
    int b = (blockIdx.x * blockDim.x + threadIdx.x) * 2;
    #pragma unroll
    for (int j = 0; j < 2; j++) {
        int e = b + j;
        if (e < EE) {
            int s = ei[e];
            int d = ei[EE + e];
            atomicAdd(&g_deg[d], 1);
            atomicAdd(&g_deg[NN + s], 1);
        }
    }
}

// Single-block exclusive scan over 2*NN degree counts -> row offsets + cursors.
__global__ void __launch_bounds__(SCAN_T) k_scan() {
    __shared__ int sums[SCAN_T];
    const int total = 2 * NN;
    const int C = (total + SCAN_T - 1) / SCAN_T;     // 98
    int t = threadIdx.x;
    int beg = t * C;
    int end = beg + C; if (end > total) end = total;
    int s = 0;
    for (int i = beg; i < end; i++) s += g_deg[i];
    sums[t] = s;
    __syncthreads();
    for (int off = 1; off < SCAN_T; off <<= 1) {
        int v = (t >= off) ? sums[t - off] : 0;
        __syncthreads();
        sums[t] += v;
        __syncthreads();
    }
    int base = (t == 0) ? 0 : sums[t - 1];           // exclusive prefix
    for (int i = beg; i < end; i++) {
        int d = g_deg[i];
        g_off[i] = base;
        g_cur[i] = base;
        base += d;
    }
}

// 2 edges per thread for atomic MLP
__global__ void k_fill(const int* __restrict__ ei) {
    int b = (blockIdx.x * blockDim.x + threadIdx.x) * 2;
    #pragma unroll
    for (int j = 0; j < 2; j++) {
        int e = b + j;
        if (e < EE) {
            int s = ei[e];
            int d = ei[EE + e];
            int pf = atomicAdd(&g_cur[d], 1);
            g_csr[pf] = s;
            int pb = atomicAdd(&g_cur[NN + s], 1);
            g_csr[pb] = d;
        }
    }
}

// Fused dual GEMM + dinv row scale. Each block: 64 rows, 256 threads.
__global__ void __launch_bounds__(GEMM_THREADS)
k_gemm(const float* __restrict__ x,
       const float* __restrict__ Wf,
       const float* __restrict__ Wb) {
    extern __shared__ float sm[];
    float* sW = sm;                 // 128*128 floats (64 KB)
    float* sX = sm + DD * DD;       // 64*128 floats (32 KB)
    const int row0 = blockIdx.x * ROWS_PER_BLOCK;
    const int tid  = threadIdx.x;
    const int warp = tid >> 5, lane = tid & 31;

    for (int i = tid; i < ROWS_PER_BLOCK * DD / 4; i += GEMM_THREADS) {
        int r  = i >> 5;
        int gr = row0 + r;
        float4 v = make_float4(0.f, 0.f, 0.f, 0.f);
        if (gr < NN) v = reinterpret_cast<const float4*>(x)[(size_t)gr * 32 + (i & 31)];
        reinterpret_cast<float4*>(sX)[i] = v;
    }

    #pragma unroll
    for (int pass = 0; pass < 2; pass++) {
        const float* W = pass ? Wb : Wf;
        __syncthreads();
        for (int i = tid; i < DD * DD / 4; i += GEMM_THREADS)
            reinterpret_cast<float4*>(sW)[i] = reinterpret_cast<const float4*>(W)[i];
        __syncthreads();

        float4 acc[8];
        #pragma unroll
        for (int r = 0; r < 8; r++) acc[r] = make_float4(0.f, 0.f, 0.f, 0.f);

        const float* xbase = sX + (warp * 8) * DD;
        #pragma unroll 4
        for (int k4 = 0; k4 < 32; k4++) {
            float4 xv[8];
            #pragma unroll
            for (int r = 0; r < 8; r++)
                xv[r] = reinterpret_cast<const float4*>(xbase + (size_t)r * DD)[k4];
            #pragma unroll
            for (int kk = 0; kk < 4; kk++) {
                float4 w = reinterpret_cast<const float4*>(sW)[(k4 * 4 + kk) * 32 + lane];
                #pragma unroll
                for (int r = 0; r < 8; r++) {
                    float xs = (kk == 0) ? xv[r].x : (kk == 1) ? xv[r].y
                             : (kk == 2) ? xv[r].z : xv[r].w;
                    acc[r].x += xs * w.x;
                    acc[r].y += xs * w.y;
                    acc[r].z += xs * w.z;
                    acc[r].w += xs * w.w;
                }
            }
        }

        float* hs = pass ? g_hs_b : g_hs_f;
        const int degoff = pass ? NN : 0;
        #pragma unroll
        for (int r = 0; r < 8; r++) {
            int gr = row0 + warp * 8 + r;
            if (gr < NN) {
                float dinv = rsqrtf((float)(g_deg[degoff + gr] + 1));   // +1 self-loop
                float4 o = acc[r];
                o.x *= dinv; o.y *= dinv; o.z *= dinv; o.w *= dinv;
                reinterpret_cast<float4*>(hs)[(size_t)gr * 32 + lane] = o;
            }
        }
    }
}

// Pull aggregation v2: 2 warps per node (one per conv), 4 nodes per 256-thread block.
// Unroll-8 index preload for 8 gathers in flight per warp; smem combine + fused finalize.
__global__ void __launch_bounds__(256)
k_agg(const float* __restrict__ bf,
      const float* __restrict__ bb,
      float* __restrict__ out) {
    __shared__ float s_part[4][DD];
    const int wb   = threadIdx.x >> 5;      // 0..7
    const int lane = threadIdx.x & 31;
    const int pair = wb >> 1;               // 0..3
    const int c    = wb & 1;                // 0 = fwd, 1 = bwd
    const int v    = blockIdx.x * 4 + pair; // NN = 50000 = 12500 * 4, no tail

    const float4* hs = reinterpret_cast<const float4*>(c ? g_hs_b : g_hs_f);
    const int degoff = c ? NN : 0;
    const int deg = g_deg[degoff + v];
    const int beg = g_off[degoff + v];

    float4 a0 = hs[(size_t)v * 32 + lane];  // self loop
    float4 a1 = make_float4(0.f, 0.f, 0.f, 0.f);

    int i = beg;
    const int end = beg + deg;
    for (; i + 8 <= end; i += 8) {
        int idx[8];
        #pragma unroll
        for (int j = 0; j < 8; j++) idx[j] = g_csr[i + j];
        float4 t[8];
        #pragma unroll
        for (int j = 0; j < 8; j++) t[j] = hs[(size_t)idx[j] * 32 + lane];
        #pragma unroll
        for (int j = 0; j < 8; j += 2) {
            a0.x += t[j].x;   a0.y += t[j].y;   a0.z += t[j].z;   a0.w += t[j].w;
            a1.x += t[j+1].x; a1.y += t[j+1].y; a1.z += t[j+1].z; a1.w += t[j+1].w;
        }
    }
    for (; i < end; i++) {
        int idx = g_csr[i];
        float4 t = hs[(size_t)idx * 32 + lane];
        a0.x += t.x; a0.y += t.y; a0.z += t.z; a0.w += t.w;
    }
    a0.x += a1.x; a0.y += a1.y; a0.z += a1.z; a0.w += a1.w;

    float dinv = rsqrtf((float)(deg + 1));
    a0.x *= dinv; a0.y *= dinv; a0.z *= dinv; a0.w *= dinv;

    if (c) reinterpret_cast<float4*>(s_part[pair])[lane] = a0;
    __syncthreads();
    if (!c) {
        float4 pb4 = reinterpret_cast<const float4*>(s_part[pair])[lane];
        float4 vf = reinterpret_cast<const float4*>(bf)[lane];
        float4 vb = reinterpret_cast<const float4*>(bb)[lane];
        float4 o;
        o.x = fmaxf(a0.x + pb4.x + vf.x + vb.x, 0.f);
        o.y = fmaxf(a0.y + pb4.y + vf.y + vb.y, 0.f);
        o.z = fmaxf(a0.z + pb4.z + vf.z + vb.z, 0.f);
        o.w = fmaxf(a0.w + pb4.w + vf.w + vb.w, 0.f);
        reinterpret_cast<float4*>(out)[(size_t)v * 32 + lane] = o;
    }
}

extern "C" void kernel_launch(void* const* d_in, const int* in_sizes, int n_in,
                              void* d_out, int out_size) {
    const float* x  = (const float*)d_in[0];
    const int*   ei = (const int*)  d_in[1];
    const float* Wf = (const float*)d_in[2];
    const float* bf = (const float*)d_in[3];
    const float* Wb = (const float*)d_in[4];
    const float* bb = (const float*)d_in[5];
    float*       out = (float*)d_out;

    const int smem = (DD * DD + ROWS_PER_BLOCK * DD) * (int)sizeof(float); // 96 KB
    cudaFuncSetAttribute(k_gemm, cudaFuncAttributeMaxDynamicSharedMemorySize, smem);

    k_init_deg<<<(2 * NN + 255) / 256, 256>>>();
    k_count<<<(EE / 2 + 255) / 256, 256>>>(ei);
    k_scan<<<1, SCAN_T>>>();
    k_fill<<<(EE / 2 + 255) / 256, 256>>>(ei);
    k_gemm<<<(NN + ROWS_PER_BLOCK - 1) / ROWS_PER_BLOCK, GEMM_THREADS, smem>>>(x, Wf, Wb);
    k_agg<<<NN / 4, 256>>>(bf, bb, out);     // 12500 blocks, 2 warps/node
}

// round 5
// speedup vs baseline: 1.4577x; 1.4577x over previous
#include <cuda_runtime.h>
#include <math.h>

#define NN 50000
#define EE 625000
#define DD 128
#define ROWS_PER_BLOCK 64
#define GEMM_THREADS 256

typedef unsigned long long u64;

// Scratch (device globals — no allocation allowed in kernel_launch)
__device__ int   g_deg[2 * NN];                 // [0:NN) fwd in-deg(+self) by dst, [NN:2NN) bwd by src
__device__ float g_hs_f[(size_t)NN * DD];       // (x@W_fwd) * dinv_f  (row-scaled)
__device__ float g_hs_b[(size_t)NN * DD];
__device__ float g_acc_f[(size_t)NN * DD];      // accumulators, init = hs (self loop)
__device__ float g_acc_b[(size_t)NN * DD];

__device__ __forceinline__ u64 pack2(float a, float b) {
    u64 r; asm("mov.b64 %0, {%1, %2};" : "=l"(r) : "f"(a), "f"(b)); return r;
}
__device__ __forceinline__ void unpack2(u64 v, float& a, float& b) {
    asm("mov.b64 {%0, %1}, %2;" : "=f"(a), "=f"(b) : "l"(v));
}
__device__ __forceinline__ void ffma2(u64& d, u64 a, u64 b) {
    asm("fma.rn.f32x2 %0, %1, %2, %3;" : "=l"(d) : "l"(a), "l"(b), "l"(d));
}
__device__ __forceinline__ u64 fmul2(u64 a, u64 b) {
    u64 r; asm("mul.rn.f32x2 %0, %1, %2;" : "=l"(r) : "l"(a), "l"(b)); return r;
}

__global__ void k_init_deg() {
    int i = blockIdx.x * blockDim.x + threadIdx.x;
    if (i < 2 * NN) g_deg[i] = 1;               // self-loop contributes 1
}

// 2 edges per thread for atomic MLP
__global__ void k_count(const int* __restrict__ ei) {
    int b = (blockIdx.x * blockDim.x + threadIdx.x) * 2;
    #pragma unroll
    for (int j = 0; j < 2; j++) {
        int e = b + j;
        if (e < EE) {
            int s = ei[e];
            int d = ei[EE + e];
            atomicAdd(&g_deg[d], 1);            // fwd conv: degree by dst
            atomicAdd(&g_deg[NN + s], 1);       // bwd conv (reversed): by src
        }
    }
}

// Fused dual GEMM + dinv row scale, FFMA2 (f32x2) inner product.
// Each block: 64 rows, 256 threads. Warp: 8 rows x 128 cols; lane owns 4 cols.
__global__ void __launch_bounds__(GEMM_THREADS)
k_gemm(const float* __restrict__ x,
       const float* __restrict__ Wf,
       const float* __restrict__ Wb) {
    extern __shared__ float sm[];
    float* sW = sm;                 // 128*128 floats (64 KB)
    float* sX = sm + DD * DD;       // 64*128 floats (32 KB)
    const int row0 = blockIdx.x * ROWS_PER_BLOCK;
    const int tid  = threadIdx.x;
    const int warp = tid >> 5, lane = tid & 31;

    for (int i = tid; i < ROWS_PER_BLOCK * DD / 4; i += GEMM_THREADS) {
        int r  = i >> 5;
        int gr = row0 + r;
        float4 v = make_float4(0.f, 0.f, 0.f, 0.f);
        if (gr < NN) v = reinterpret_cast<const float4*>(x)[(size_t)gr * 32 + (i & 31)];
        reinterpret_cast<float4*>(sX)[i] = v;
    }

    #pragma unroll
    for (int pass = 0; pass < 2; pass++) {
        const float* W = pass ? Wb : Wf;
        __syncthreads();
        for (int i = tid; i < DD * DD / 4; i += GEMM_THREADS)
            reinterpret_cast<float4*>(sW)[i] = reinterpret_cast<const float4*>(W)[i];
        __syncthreads();

        u64 acc[8][2];
        #pragma unroll
        for (int r = 0; r < 8; r++) { acc[r][0] = pack2(0.f, 0.f); acc[r][1] = acc[r][0]; }

        const float* xbase = sX + (warp * 8) * DD;
        #pragma unroll 2
        for (int k4 = 0; k4 < 32; k4++) {
            float4 xv[8];
            #pragma unroll
            for (int r = 0; r < 8; r++)
                xv[r] = reinterpret_cast<const float4*>(xbase + (size_t)r * DD)[k4];
            #pragma unroll
            for (int kk = 0; kk < 4; kk++) {
                ulonglong2 w2 = reinterpret_cast<const ulonglong2*>(sW)[(k4 * 4 + kk) * 32 + lane];
                #pragma unroll
                for (int r = 0; r < 8; r++) {
                    float xs = (kk == 0) ? xv[r].x : (kk == 1) ? xv[r].y
                             : (kk == 2) ? xv[r].z : xv[r].w;
                    u64 xs2 = pack2(xs, xs);
                    ffma2(acc[r][0], w2.x, xs2);
                    ffma2(acc[r][1], w2.y, xs2);
                }
            }
        }

        float* hs = pass ? g_hs_b  : g_hs_f;
        float* ac = pass ? g_acc_b : g_acc_f;
        const int degoff = pass ? NN : 0;
        #pragma unroll
        for (int r = 0; r < 8; r++) {
            int gr = row0 + warp * 8 + r;
            if (gr < NN) {
                float dinv = rsqrtf((float)g_deg[degoff + gr]);
                u64 d2 = pack2(dinv, dinv);
                ulonglong2 o;
                o.x = fmul2(acc[r][0], d2);
                o.y = fmul2(acc[r][1], d2);
                reinterpret_cast<ulonglong2*>(hs)[(size_t)gr * 32 + lane] = o;
                reinterpret_cast<ulonglong2*>(ac)[(size_t)gr * 32 + lane] = o;
            }
        }
    }
}

// One warp per edge, BOTH convs: gather hs_f[s] -> red acc_f[d]; gather hs_b[d] -> red acc_b[s].
__global__ void k_scatter(const int* __restrict__ ei) {
    unsigned gw = (blockIdx.x * blockDim.x + threadIdx.x) >> 5;
    int lane = threadIdx.x & 31;
    if (gw >= (unsigned)EE) return;
    int s = ei[gw];
    int d = ei[EE + gw];
    const float4* hsf = reinterpret_cast<const float4*>(g_hs_f);
    const float4* hsb = reinterpret_cast<const float4*>(g_hs_b);
    float4 vf = hsf[(size_t)s * 32 + lane];     // two independent gathers in flight
    float4 vb = hsb[(size_t)d * 32 + lane];
    float* pf = g_acc_f + (size_t)d * DD + lane * 4;
    float* pb = g_acc_b + (size_t)s * DD + lane * 4;
    asm volatile("red.global.add.v4.f32 [%0], {%1, %2, %3, %4};"
                 :: "l"(pf), "f"(vf.x), "f"(vf.y), "f"(vf.z), "f"(vf.w) : "memory");
    asm volatile("red.global.add.v4.f32 [%0], {%1, %2, %3, %4};"
                 :: "l"(pb), "f"(vb.x), "f"(vb.y), "f"(vb.z), "f"(vb.w) : "memory");
}

// out = relu(dinv_f*acc_f + dinv_b*acc_b + b_f + b_b)
__global__ void k_finalize(const float* __restrict__ bf,
                           const float* __restrict__ bb,
                           float* __restrict__ out) {
    int i = blockIdx.x * blockDim.x + threadIdx.x;      // over NN*32 float4s
    if (i >= NN * 32) return;
    int v  = i >> 5;
    int c4 = i & 31;
    float df = rsqrtf((float)g_deg[v]);
    float db = rsqrtf((float)g_deg[NN + v]);
    float4 af = reinterpret_cast<const float4*>(g_acc_f)[i];
    float4 ab = reinterpret_cast<const float4*>(g_acc_b)[i];
    float4 vf = reinterpret_cast<const float4*>(bf)[c4];
    float4 vb = reinterpret_cast<const float4*>(bb)[c4];
    float4 o;
    o.x = fmaxf(af.x * df + ab.x * db + vf.x + vb.x, 0.f);
    o.y = fmaxf(af.y * df + ab.y * db + vf.y + vb.y, 0.f);
    o.z = fmaxf(af.z * df + ab.z * db + vf.z + vb.z, 0.f);
    o.w = fmaxf(af.w * df + ab.w * db + vf.w + vb.w, 0.f);
    reinterpret_cast<float4*>(out)[i] = o;
}

extern "C" void kernel_launch(void* const* d_in, const int* in_sizes, int n_in,
                              void* d_out, int out_size) {
    const float* x  = (const float*)d_in[0];
    const int*   ei = (const int*)  d_in[1];
    const float* Wf = (const float*)d_in[2];
    const float* bf = (const float*)d_in[3];
    const float* Wb = (const float*)d_in[4];
    const float* bb = (const float*)d_in[5];
    float*       out = (float*)d_out;

    const int smem = (DD * DD + ROWS_PER_BLOCK * DD) * (int)sizeof(float); // 96 KB
    cudaFuncSetAttribute(k_gemm, cudaFuncAttributeMaxDynamicSharedMemorySize, smem);

    k_init_deg<<<(2 * NN + 255) / 256, 256>>>();
    k_count<<<(EE / 2 + 255) / 256, 256>>>(ei);
    k_gemm<<<(NN + ROWS_PER_BLOCK - 1) / ROWS_PER_BLOCK, GEMM_THREADS, smem>>>(x, Wf, Wb);
    k_scatter<<<(EE * 32u + 255u) / 256u, 256>>>(ei);    // 1 warp per edge, both convs
    k_finalize<<<(NN * 32 + 255) / 256, 256>>>(bf, bb, out);
}